// round 16
// baseline (speedup 1.0000x reference)
#include <cuda_runtime.h>
#include <cstdint>
#include <cstddef>

#define NB    4
#define CIN   512
#define NPIX  4096
#define CQK   256
#define COUT  512

#define ROWB    144              // padded smem row bytes (128B data + 16B pad)
#define TM      64
#define THREADS 128
#define NST     3
#define STG     ((TM + 64) * ROWB)   // 18432
#define GSMEM   (STG * NST)          // 55296 -> 3 CTAs/SM (166 KB)
#define INV252  (1.0f/252.0f)
#define SSCALE  2048.0f
#define INVSSCALE (1.0f/2048.0f)

// -------------------- scratch (device globals) ----------------------------
__device__ int8_t  g_Xq2[(size_t)NB*NPIX*2*CIN];
__device__ int8_t  g_Xk2[(size_t)NB*NPIX*2*CIN];
__device__ int8_t  g_Wq2[CQK*2*CIN];
__device__ int8_t  g_Wk2[CQK*2*CIN];
__device__ int8_t  g_Wv2[COUT*2*CIN];
__device__ float   g_Qf[(size_t)NB*NPIX*CQK];
__device__ float   g_Kf[(size_t)NB*NPIX*CQK];
__device__ float   g_Vf[(size_t)NB*COUT*NPIX];
__device__ int8_t  g_Q2[(size_t)NB*NPIX*2*CQK];
__device__ int8_t  g_K2[(size_t)NB*NPIX*2*CQK];
__device__ int8_t  g_V2[(size_t)NB*COUT*2*NPIX];
__device__ int16_t g_S [(size_t)NB*NPIX*NPIX];
__device__ int8_t  g_A2[(size_t)NB*NPIX*2*NPIX];
__device__ float g_sXq[NB*NPIX], g_sXk[NB*NPIX];
__device__ float g_sWq[CQK], g_sWk[CQK], g_sWv[COUT];
__device__ float g_sQ[NB*NPIX], g_sK[NB*NPIX], g_sV[NB*COUT], g_sAt[NB*NPIX];

// -------------------- PTX helpers -----------------------------------------
__device__ __forceinline__ uint32_t s2u(const void* p) {
    uint32_t a;
    asm("{ .reg .u64 t; cvta.to.shared.u64 t, %1; cvt.u32.u64 %0, t; }" : "=r"(a) : "l"(p));
    return a;
}
__device__ __forceinline__ void cp16(uint32_t s, const void* g) {
    asm volatile("cp.async.cg.shared.global [%0], [%1], 16;" :: "r"(s), "l"(g));
}
#define CP_COMMIT() asm volatile("cp.async.commit_group;" ::: "memory")
#define CP_WAIT1()  asm volatile("cp.async.wait_group 1;" ::: "memory")

__device__ __forceinline__ void ldm4(uint32_t& r0, uint32_t& r1, uint32_t& r2, uint32_t& r3,
                                     uint32_t a) {
    asm volatile("ldmatrix.sync.aligned.m8n8.x4.shared.b16 {%0,%1,%2,%3}, [%4];"
                 : "=r"(r0), "=r"(r1), "=r"(r2), "=r"(r3) : "r"(a));
}
__device__ __forceinline__ void mma16832(int* d, const uint32_t* a, uint32_t b0, uint32_t b1) {
    asm volatile(
      "mma.sync.aligned.m16n8k32.row.col.s32.s8.s8.s32 "
      "{%0,%1,%2,%3},{%4,%5,%6,%7},{%8,%9},{%0,%1,%2,%3};"
      : "+r"(d[0]), "+r"(d[1]), "+r"(d[2]), "+r"(d[3])
      : "r"(a[0]), "r"(a[1]), "r"(a[2]), "r"(a[3]), "r"(b0), "r"(b1));
}

// -------------------- canonical int8 Ozaki GEMM ---------------------------
// D[M,N] = scale * sigA[m]*sigB[n]*(acc0 + acc1/252) + biases.
// Physical rows [q1|q2] (2K bytes); logical 128B chunks A:[q1|q1|q2],
// B:[q1|q2|q1] via remap; chunks < K/128 -> acc0, rest -> acc1.
// Tile 64x64, 128 thr (4 warps 2x2, warp 32x32), 3-stage cp.async,
// 3 CTAs/SM, ldmatrix fragments double-buffered across ks-steps.
// EPI 0: fp32 out.  EPI 1: int16 out (value * SSCALE, clamped).
template<int EPI>
__global__ void __launch_bounds__(THREADS, 3)
gemm_s8(const int8_t* __restrict__ A, size_t sA,
        const int8_t* __restrict__ B, size_t sB,
        int K,
        float* __restrict__ Cf, int16_t* __restrict__ Cs, size_t ldc, size_t sC,
        const float* __restrict__ sAarr, size_t sAstr,
        const float* __restrict__ sBarr, size_t sBstr,
        const float* __restrict__ bias_row, const float* __restrict__ bias_col,
        float scale)
{
    extern __shared__ __align__(128) char smem[];
    const uint32_t sb = s2u(smem);
    const int tid = threadIdx.x, lane = tid & 31, wid = tid >> 5;
    const int wm0 = (wid & 1) * 32;
    const int wn0 = (wid >> 1) * 32;
    const int m0 = blockIdx.y * TM, n0 = blockIdx.x * 64, z = blockIdx.z;

    const int n1 = K / 128;
    const int nk = 3 * n1;
    const int rowlen = 2 * K;

    A += (size_t)z * sA + (size_t)m0 * rowlen;
    B += (size_t)z * sB + (size_t)n0 * rowlen;

    auto load_stage = [&](int st, int kc) {
        const int ca = (kc < n1) ? kc : kc - n1;          // A: [q1|q1|q2]
        const int cb = (kc < 2 * n1) ? kc : kc - 2 * n1;  // B: [q1|q2|q1]
        const int8_t* ga = A + (size_t)ca * 128;
        const int8_t* gb = B + (size_t)cb * 128;
        uint32_t sa = sb + st * STG;
        uint32_t sbm = sa + TM * ROWB;
        #pragma unroll
        for (int i = 0; i < 8; i++) {
            const int idx = tid + i * THREADS;   // 128 rows x 8 chunks
            const int row = idx >> 3, ch = idx & 7;
            if (row < TM)
                cp16(sa + row * ROWB + ch * 16, ga + (size_t)row * rowlen + ch * 16);
            else
                cp16(sbm + (row - TM) * ROWB + ch * 16,
                     gb + (size_t)(row - TM) * rowlen + ch * 16);
        }
    };

    int acc0[2][4][4], acc1[2][4][4];
    #pragma unroll
    for (int i = 0; i < 2; i++)
        #pragma unroll
        for (int j = 0; j < 4; j++)
            #pragma unroll
            for (int q = 0; q < 4; q++) { acc0[i][j][q] = 0; acc1[i][j][q] = 0; }

    load_stage(0, 0); CP_COMMIT();
    load_stage(1, 1); CP_COMMIT();

    const int arow = wm0 + (lane & 15);
    const int acsel = (lane >> 4);
    const int brow = wn0 + (lane & 7) + ((lane >> 4) & 1) * 8;
    const int bcsel = (lane >> 3) & 1;

    // double-buffered fragments
    uint32_t afr[2][2][4], bfr[2][2][4];

    for (int k = 0; k < nk; k++) {
        CP_WAIT1();            // groups 0..k complete
        __syncthreads();       // slot (k+2)%3 == (k-1)%3 free to overwrite
        if (k + 2 < nk) load_stage((k + 2) % NST, k + 2);
        CP_COMMIT();

        const uint32_t sa = sb + (k % NST) * STG;
        const uint32_t sbm = sa + TM * ROWB;

        // preload fragments for ks=0
        {
            const uint32_t ac = acsel * 16;
            ldm4(afr[0][0][0], afr[0][0][1], afr[0][0][2], afr[0][0][3],
                 sa + arow * ROWB + ac);
            ldm4(afr[0][1][0], afr[0][1][1], afr[0][1][2], afr[0][1][3],
                 sa + (arow + 16) * ROWB + ac);
            const uint32_t bc = bcsel * 16;
            ldm4(bfr[0][0][0], bfr[0][0][1], bfr[0][0][2], bfr[0][0][3],
                 sbm + brow * ROWB + bc);
            ldm4(bfr[0][1][0], bfr[0][1][1], bfr[0][1][2], bfr[0][1][3],
                 sbm + (brow + 16) * ROWB + bc);
        }

        #pragma unroll
        for (int ks = 0; ks < 4; ks++) {
            const int cur = ks & 1, nxt = cur ^ 1;
            if (ks < 3) {      // prefetch ks+1 fragments before current mma
                const uint32_t ac = ((ks + 1) * 2 + acsel) * 16;
                ldm4(afr[nxt][0][0], afr[nxt][0][1], afr[nxt][0][2], afr[nxt][0][3],
                     sa + arow * ROWB + ac);
                ldm4(afr[nxt][1][0], afr[nxt][1][1], afr[nxt][1][2], afr[nxt][1][3],
                     sa + (arow + 16) * ROWB + ac);
                const uint32_t bc = ((ks + 1) * 2 + bcsel) * 16;
                ldm4(bfr[nxt][0][0], bfr[nxt][0][1], bfr[nxt][0][2], bfr[nxt][0][3],
                     sbm + brow * ROWB + bc);
                ldm4(bfr[nxt][1][0], bfr[nxt][1][1], bfr[nxt][1][2], bfr[nxt][1][3],
                     sbm + (brow + 16) * ROWB + bc);
            }
            if (k < n1) {
                #pragma unroll
                for (int i = 0; i < 2; i++)
                    #pragma unroll
                    for (int jn = 0; jn < 4; jn++)
                        mma16832(acc0[i][jn], afr[cur][i],
                                 bfr[cur][jn >> 1][(jn & 1) * 2],
                                 bfr[cur][jn >> 1][(jn & 1) * 2 + 1]);
            } else {
                #pragma unroll
                for (int i = 0; i < 2; i++)
                    #pragma unroll
                    for (int jn = 0; jn < 4; jn++)
                        mma16832(acc1[i][jn], afr[cur][i],
                                 bfr[cur][jn >> 1][(jn & 1) * 2],
                                 bfr[cur][jn >> 1][(jn & 1) * 2 + 1]);
            }
        }
    }

    // -------- epilogue --------
    const int mb = m0 + wm0 + (lane >> 2);
    const int nb = n0 + wn0 + (lane & 3) * 2;
    #pragma unroll
    for (int i = 0; i < 2; i++) {
        #pragma unroll
        for (int half = 0; half < 2; half++) {
            const int m = mb + i * 16 + half * 8;
            const float sAm = sAarr[z * sAstr + m] * scale;
            const float br = bias_row ? bias_row[m] : 0.f;
            #pragma unroll
            for (int jn = 0; jn < 4; jn++) {
                const int n = nb + jn * 8;
                float f0 = (float)acc0[i][jn][half * 2 + 0]
                         + (float)acc1[i][jn][half * 2 + 0] * INV252;
                float f1 = (float)acc0[i][jn][half * 2 + 1]
                         + (float)acc1[i][jn][half * 2 + 1] * INV252;
                float v0 = f0 * sAm * sBarr[z * sBstr + n] + br;
                float v1 = f1 * sAm * sBarr[z * sBstr + n + 1] + br;
                if (bias_col) { v0 += bias_col[n]; v1 += bias_col[n + 1]; }
                if (EPI == 0) {
                    *(float2*)&Cf[(size_t)z * sC + (size_t)m * ldc + n] = make_float2(v0, v1);
                } else {
                    float q0 = fminf(fmaxf(v0 * SSCALE, -32000.f), 32000.f);
                    float q1 = fminf(fmaxf(v1 * SSCALE, -32000.f), 32000.f);
                    short2 o;
                    o.x = (short)(int)rintf(q0);
                    o.y = (short)(int)rintf(q1);
                    *(short2*)&Cs[(size_t)z * sC + (size_t)m * ldc + n] = o;
                }
            }
        }
    }
}

// -------------------- quantization helpers --------------------------------
__device__ __forceinline__ float clamp127(float q) {
    return fminf(127.f, fmaxf(-127.f, q));
}

__device__ __forceinline__ void rowquant_body(const float* __restrict__ src, int len,
                                              int8_t* __restrict__ dst,
                                              float* __restrict__ sOut)
{
    const int t = threadIdx.x;
    float m = 0.f;
    for (int i = t; i < len; i += 256) m = fmaxf(m, fabsf(src[i]));
    #pragma unroll
    for (int o = 16; o > 0; o >>= 1) m = fmaxf(m, __shfl_xor_sync(~0u, m, o));
    __shared__ float sm[8];
    if ((t & 31) == 0) sm[t >> 5] = m;
    __syncthreads();
    float mm = sm[0];
    #pragma unroll
    for (int i = 1; i < 8; i++) mm = fmaxf(mm, sm[i]);

    const float s1 = mm * (1.f / 127.f);
    const float i1 = (mm > 0.f) ? (127.f / mm) : 0.f;
    const float i2 = i1 * 252.f;

    for (int i = t; i < len; i += 256) {
        float x = src[i];
        float q1 = clamp127(rintf(x * i1));
        float r = x - q1 * s1;
        float q2 = clamp127(rintf(r * i2));
        dst[i] = (int8_t)(int)q1;
        dst[len + i] = (int8_t)(int)q2;
    }
    if (t == 0) *sOut = s1;
}

__global__ void __launch_bounds__(256)
rowquantW(const float* __restrict__ Wq, const float* __restrict__ Wk,
          const float* __restrict__ Wv,
          int8_t* __restrict__ Wq2, int8_t* __restrict__ Wk2, int8_t* __restrict__ Wv2,
          float* __restrict__ sWq, float* __restrict__ sWk, float* __restrict__ sWv)
{
    const int r = blockIdx.x;
    const float* src; int8_t* dst; float* sOut;
    if (r < CQK)            { src = Wq + (size_t)r * CIN;          dst = Wq2 + (size_t)r * 2 * CIN;          sOut = sWq + r; }
    else if (r < 2 * CQK)   { int rr = r - CQK;   src = Wk + (size_t)rr * CIN; dst = Wk2 + (size_t)rr * 2 * CIN; sOut = sWk + rr; }
    else                    { int rr = r - 2*CQK; src = Wv + (size_t)rr * CIN; dst = Wv2 + (size_t)rr * 2 * CIN; sOut = sWv + rr; }
    rowquant_body(src, CIN, dst, sOut);
}

__global__ void __launch_bounds__(256)
rowquantQK(const float* __restrict__ Qf, const float* __restrict__ Kf,
           int8_t* __restrict__ Q2, int8_t* __restrict__ K2,
           float* __restrict__ sQ, float* __restrict__ sK)
{
    const size_t r = blockIdx.x;
    const size_t nrows = (size_t)NB * NPIX;
    if (r < nrows)
        rowquant_body(Qf + r * CQK, CQK, Q2 + r * 2 * CQK, sQ + r);
    else {
        const size_t rr = r - nrows;
        rowquant_body(Kf + rr * CQK, CQK, K2 + rr * 2 * CQK, sK + rr);
    }
}

__global__ void __launch_bounds__(256)
rowquantV(const float* __restrict__ Vf, int8_t* __restrict__ V2, float* __restrict__ sV)
{
    const size_t r = blockIdx.x;
    rowquant_body(Vf + r * NPIX, NPIX, V2 + r * 2 * NPIX, sV + r);
}

// Chunked column-max with atomicMax (non-negative floats as ints: monotone;
// deterministic across graph replays). grid (NPIX/256, NB, 8).
__global__ void __launch_bounds__(256)
colmax8(const float* __restrict__ Xq, const float* __restrict__ Xk,
        float* __restrict__ sXq, float* __restrict__ sXk)
{
    const int n = blockIdx.x * 256 + threadIdx.x;
    const int b = blockIdx.y;
    const int zz = blockIdx.z;
    const float* X = (zz & 1) ? Xk : Xq;
    float* sX = (zz & 1) ? sXk : sXq;
    const int c0 = (zz >> 1) * (CIN / 4);
    const float* p = X + (size_t)b * CIN * NPIX + (size_t)c0 * NPIX + n;
    float m = 0.f;
    for (int ci = 0; ci < CIN / 4; ci++) m = fmaxf(m, fabsf(p[(size_t)ci * NPIX]));
    atomicMax((int*)&sX[b * NPIX + n], __float_as_int(m * (1.f / 127.f)));
}

// Merged transpose + quantize for both inputs: grid (NPIX/32, CIN/32, 2*NB)
__global__ void __launch_bounds__(256)
transpose_quant2(const float* __restrict__ Xq, const float* __restrict__ Xk,
                 const float* __restrict__ sXq, const float* __restrict__ sXk,
                 int8_t* __restrict__ Xq2, int8_t* __restrict__ Xk2)
{
    __shared__ float t[32][33];
    const int zz = blockIdx.z;
    const int b = zz & (NB - 1);
    const int which = zz >> 2;
    const float* X = which ? Xk : Xq;
    const float* sX = which ? sXk : sXq;
    int8_t* X2 = which ? Xk2 : Xq2;

    const int n0 = blockIdx.x * 32, c0 = blockIdx.y * 32;
    const int tx = threadIdx.x & 31, ty = threadIdx.x >> 5;
    const float* Xb = X + (size_t)b * CIN * NPIX;
    #pragma unroll
    for (int r = 0; r < 4; r++)
        t[ty + r * 8][tx] = Xb[(size_t)(c0 + ty + r * 8) * NPIX + n0 + tx];
    __syncthreads();
    const size_t ob = (size_t)b * NPIX * 2 * CIN;
    #pragma unroll
    for (int r = 0; r < 4; r++) {
        const int n = n0 + ty + r * 8;
        const int c = c0 + tx;
        const float v = t[tx][ty + r * 8];
        const float s1 = sX[b * NPIX + n];
        const float i1 = (s1 > 0.f) ? (1.f / s1) : 0.f;
        float q1 = clamp127(rintf(v * i1));
        float rr = v - q1 * s1;
        float q2 = clamp127(rintf(rr * i1 * 252.f));
        const size_t row = ob + (size_t)n * (2 * CIN);
        X2[row + c] = (int8_t)(int)q1;
        X2[row + CIN + c] = (int8_t)(int)q2;
    }
}

// -------- softmax: int16 S rows -> int8 attn [q1|q2] + scale ---------------
__global__ void __launch_bounds__(256)
softmax2_q(const int16_t* __restrict__ S, int8_t* __restrict__ A2,
           float* __restrict__ sAt)
{
    const size_t rb = (size_t)blockIdx.x * NPIX;
    const int16_t* row = S + rb;
    int8_t* orow = A2 + (size_t)blockIdx.x * (2 * NPIX);
    const int t = threadIdx.x;
    float v[16];
    float m = -1e30f;
    #pragma unroll
    for (int i = 0; i < 16; i++) {
        v[i] = (float)row[t + i * 256] * INVSSCALE;
        m = fmaxf(m, v[i]);
    }
    #pragma unroll
    for (int o = 16; o > 0; o >>= 1) m = fmaxf(m, __shfl_xor_sync(~0u, m, o));
    __shared__ float smax[8], ssum[8];
    if ((t & 31) == 0) smax[t >> 5] = m;
    __syncthreads();
    float mm = smax[0];
    #pragma unroll
    for (int i = 1; i < 8; i++) mm = fmaxf(mm, smax[i]);
    float s = 0.f;
    #pragma unroll
    for (int i = 0; i < 16; i++) { v[i] = __expf(v[i] - mm); s += v[i]; }
    #pragma unroll
    for (int o = 16; o > 0; o >>= 1) s += __shfl_xor_sync(~0u, s, o);
    if ((t & 31) == 0) ssum[t >> 5] = s;
    __syncthreads();
    float tot = 0.f;
    #pragma unroll
    for (int i = 0; i < 8; i++) tot += ssum[i];
    const float inv = 1.0f / tot;

    #pragma unroll
    for (int i = 0; i < 16; i++) {
        const int k = t + i * 256;
        float f = v[i] * 127.f;
        float q1 = clamp127(rintf(f));
        float q2 = clamp127(rintf((f - q1) * 252.f));
        orow[k] = (int8_t)(int)q1;
        orow[NPIX + k] = (int8_t)(int)q2;
    }
    if (t == 0) sAt[blockIdx.x] = inv * (1.f / 127.f);
}

// ------------------------------- host -------------------------------------
extern "C" void kernel_launch(void* const* d_in, const int* in_sizes, int n_in,
                              void* d_out, int out_size)
{
    const float* qfeat = (const float*)d_in[0];
    const float* kfeat = (const float*)d_in[1];
    const float* Wq = (const float*)d_in[2];
    const float* bq = (const float*)d_in[3];
    const float* Wk = (const float*)d_in[4];
    const float* bk = (const float*)d_in[5];
    const float* Wv = (const float*)d_in[6];
    const float* bv = (const float*)d_in[7];
    float* out = (float*)d_out;

    void *Xq2, *Xk2, *Wq2, *Wk2, *Wv2, *Qf, *Kf, *Vf, *Q2, *K2, *V2, *Sd, *A2;
    void *sXq, *sXk, *sWq, *sWk, *sWv, *sQ, *sK, *sV, *sAt;
    cudaGetSymbolAddress(&Xq2, g_Xq2);
    cudaGetSymbolAddress(&Xk2, g_Xk2);
    cudaGetSymbolAddress(&Wq2, g_Wq2);
    cudaGetSymbolAddress(&Wk2, g_Wk2);
    cudaGetSymbolAddress(&Wv2, g_Wv2);
    cudaGetSymbolAddress(&Qf, g_Qf);
    cudaGetSymbolAddress(&Kf, g_Kf);
    cudaGetSymbolAddress(&Vf, g_Vf);
    cudaGetSymbolAddress(&Q2, g_Q2);
    cudaGetSymbolAddress(&K2, g_K2);
    cudaGetSymbolAddress(&V2, g_V2);
    cudaGetSymbolAddress(&Sd, g_S);
    cudaGetSymbolAddress(&A2, g_A2);
    cudaGetSymbolAddress(&sXq, g_sXq);
    cudaGetSymbolAddress(&sXk, g_sXk);
    cudaGetSymbolAddress(&sWq, g_sWq);
    cudaGetSymbolAddress(&sWk, g_sWk);
    cudaGetSymbolAddress(&sWv, g_sWv);
    cudaGetSymbolAddress(&sQ, g_sQ);
    cudaGetSymbolAddress(&sK, g_sK);
    cudaGetSymbolAddress(&sV, g_sV);
    cudaGetSymbolAddress(&sAt, g_sAt);

    cudaFuncSetAttribute((const void*)gemm_s8<0>, cudaFuncAttributeMaxDynamicSharedMemorySize, GSMEM);
    cudaFuncSetAttribute((const void*)gemm_s8<1>, cudaFuncAttributeMaxDynamicSharedMemorySize, GSMEM);

    // 1) weights quantization (merged)
    rowquantW<<<2 * CQK + COUT, 256>>>(Wq, Wk, Wv,
        (int8_t*)Wq2, (int8_t*)Wk2, (int8_t*)Wv2,
        (float*)sWq, (float*)sWk, (float*)sWv);

    // 2) column maxima (chunked + atomicMax)
    colmax8<<<dim3(NPIX / 256, NB, 8), 256>>>(qfeat, kfeat, (float*)sXq, (float*)sXk);

    // 3) transpose + quantize both inputs (merged)
    transpose_quant2<<<dim3(NPIX / 32, CIN / 32, 2 * NB), 256>>>(
        qfeat, kfeat, (const float*)sXq, (const float*)sXk,
        (int8_t*)Xq2, (int8_t*)Xk2);

    // 4) Q proj: M=4096, N=256, K=512
    gemm_s8<0><<<dim3(CQK / 64, NPIX / 64, NB), THREADS, GSMEM>>>(
        (const int8_t*)Xq2, (size_t)NPIX * 2 * CIN,
        (const int8_t*)Wq2, 0, CIN,
        (float*)Qf, nullptr, (size_t)CQK, (size_t)NPIX * CQK,
        (const float*)sXq, (size_t)NPIX, (const float*)sWq, 0,
        nullptr, bq, 1.0f);

    // 5) K proj  <- profiled launch slot
    gemm_s8<0><<<dim3(CQK / 64, NPIX / 64, NB), THREADS, GSMEM>>>(
        (const int8_t*)Xk2, (size_t)NPIX * 2 * CIN,
        (const int8_t*)Wk2, 0, CIN,
        (float*)Kf, nullptr, (size_t)CQK, (size_t)NPIX * CQK,
        (const float*)sXk, (size_t)NPIX, (const float*)sWk, 0,
        nullptr, bk, 1.0f);

    // 6) V proj: M=512, N=4096, K=512
    gemm_s8<0><<<dim3(NPIX / 64, COUT / 64, NB), THREADS, GSMEM>>>(
        (const int8_t*)Wv2, 0,
        (const int8_t*)Xk2, (size_t)NPIX * 2 * CIN, CIN,
        (float*)Vf, nullptr, (size_t)NPIX, (size_t)COUT * NPIX,
        (const float*)sWv, 0, (const float*)sXk, (size_t)NPIX,
        bv, nullptr, 1.0f);

    // 7) quantize Q+K (merged) and V
    rowquantQK<<<2 * NB * NPIX, 256>>>((const float*)Qf, (const float*)Kf,
        (int8_t*)Q2, (int8_t*)K2, (float*)sQ, (float*)sK);
    rowquantV<<<NB * COUT, 256>>>((const float*)Vf, (int8_t*)V2, (float*)sV);

    // 8) sim: S = int16( (1/16) Q2 . K2^T * SSCALE ), M=N=4096, K=256
    gemm_s8<1><<<dim3(NPIX / 64, NPIX / 64, NB), THREADS, GSMEM>>>(
        (const int8_t*)Q2, (size_t)NPIX * 2 * CQK,
        (const int8_t*)K2, (size_t)NPIX * 2 * CQK, CQK,
        nullptr, (int16_t*)Sd, (size_t)NPIX, (size_t)NPIX * NPIX,
        (const float*)sQ, (size_t)NPIX, (const float*)sK, (size_t)NPIX,
        nullptr, nullptr, 0.0625f);

    // 9) softmax -> int8 attn [q1|q2] + scales
    softmax2_q<<<NB * NPIX, 256>>>((const int16_t*)Sd, (int8_t*)A2, (float*)sAt);

    // 10) ctx: out = V2 . A2^T, M=512, N=4096, K=4096
    gemm_s8<0><<<dim3(NPIX / 64, COUT / 64, NB), THREADS, GSMEM>>>(
        (const int8_t*)V2, (size_t)COUT * 2 * NPIX,
        (const int8_t*)A2, (size_t)NPIX * 2 * NPIX, NPIX,
        out, nullptr, (size_t)NPIX, (size_t)COUT * NPIX,
        (const float*)sV, (size_t)COUT, (const float*)sAt, (size_t)NPIX,
        nullptr, nullptr, 1.0f);
}

// round 17
// speedup vs baseline: 1.2789x; 1.2789x over previous
#include <cuda_runtime.h>
#include <cstdint>
#include <cstddef>

#define NB    4
#define CIN   512
#define NPIX  4096
#define CQK   256
#define COUT  512

#define ROWB    144              // padded smem row bytes (128B data + 16B pad)
#define STG     (384 * ROWB)     // A_q1[128] A_q2[128] B_q1[64] B_q2[64] rows
#define NST     2
#define GSMEM   (STG * NST)      // 110592 -> 2 CTAs/SM
#define INV252  (1.0f/252.0f)
#define SSCALE  2048.0f
#define INVSSCALE (1.0f/2048.0f)

// -------------------- scratch (device globals) ----------------------------
__device__ int8_t  g_Xq2[(size_t)NB*NPIX*2*CIN];
__device__ int8_t  g_Xk2[(size_t)NB*NPIX*2*CIN];
__device__ int8_t  g_Wq2[CQK*2*CIN];
__device__ int8_t  g_Wk2[CQK*2*CIN];
__device__ int8_t  g_Wv2[COUT*2*CIN];
__device__ float   g_Qf[(size_t)NB*NPIX*CQK];
__device__ float   g_Kf[(size_t)NB*NPIX*CQK];
__device__ float   g_Vf[(size_t)NB*COUT*NPIX];
__device__ int8_t  g_Q2[(size_t)NB*NPIX*2*CQK];
__device__ int8_t  g_K2[(size_t)NB*NPIX*2*CQK];
__device__ int8_t  g_V2[(size_t)NB*COUT*2*NPIX];
__device__ int16_t g_S [(size_t)NB*NPIX*NPIX];
__device__ int8_t  g_A2[(size_t)NB*NPIX*2*NPIX];
__device__ float g_sXq[NB*NPIX], g_sXk[NB*NPIX];
__device__ float g_sWq[CQK], g_sWk[CQK], g_sWv[COUT];
__device__ float g_sQ[NB*NPIX], g_sK[NB*NPIX], g_sV[NB*COUT], g_sAt[NB*NPIX];

// -------------------- PTX helpers -----------------------------------------
__device__ __forceinline__ uint32_t s2u(const void* p) {
    uint32_t a;
    asm("{ .reg .u64 t; cvta.to.shared.u64 t, %1; cvt.u32.u64 %0, t; }" : "=r"(a) : "l"(p));
    return a;
}
__device__ __forceinline__ void cp16(uint32_t s, const void* g) {
    asm volatile("cp.async.cg.shared.global [%0], [%1], 16;" :: "r"(s), "l"(g));
}
#define CP_COMMIT() asm volatile("cp.async.commit_group;" ::: "memory")

__device__ __forceinline__ void ldm4(uint32_t* r, uint32_t a) {
    asm volatile("ldmatrix.sync.aligned.m8n8.x4.shared.b16 {%0,%1,%2,%3}, [%4];"
                 : "=r"(r[0]), "=r"(r[1]), "=r"(r[2]), "=r"(r[3]) : "r"(a));
}
__device__ __forceinline__ void mma16832(int* d, const uint32_t* a, uint32_t b0, uint32_t b1) {
    asm volatile(
      "mma.sync.aligned.m16n8k32.row.col.s32.s8.s8.s32 "
      "{%0,%1,%2,%3},{%4,%5,%6,%7},{%8,%9},{%0,%1,%2,%3};"
      : "+r"(d[0]), "+r"(d[1]), "+r"(d[2]), "+r"(d[3])
      : "r"(a[0]), "r"(a[1]), "r"(a[2]), "r"(a[3]), "r"(b0), "r"(b1));
}

// -------------------- canonical int8 Ozaki GEMM ---------------------------
// D[M,N] = scale * sigA[m]*sigB[n]*(acc0 + acc1/252) + biases.
// Physical rows [q1|q2] (2K bytes). Mainloop over PHYSICAL 128B chunks: one
// stage holds A_q1, A_q2, B_q1, B_q2 for the chunk; three mma groups reuse
// the four tiles (q1q1 -> acc0; q1*q2 + q2*q1 -> acc1). This loads each tile
// once (vs 3-segment logical loop re-loading q1 tiles). Tile 128x64, 256 thr
// (8 warps 4Mx2N, warp 32x32), 2-stage cp.async, 2 CTAs/SM.
// EPI 0: fp32 out.  EPI 1: int16 out (value * SSCALE, clamped).
template<int EPI>
__global__ void __launch_bounds__(256, 2)
gemm_s8(const int8_t* __restrict__ A, size_t sA,
        const int8_t* __restrict__ B, size_t sB,
        int K,
        float* __restrict__ Cf, int16_t* __restrict__ Cs, size_t ldc, size_t sC,
        const float* __restrict__ sAarr, size_t sAstr,
        const float* __restrict__ sBarr, size_t sBstr,
        const float* __restrict__ bias_row, const float* __restrict__ bias_col,
        float scale)
{
    extern __shared__ __align__(128) char smem[];
    const uint32_t sb = s2u(smem);
    const int tid = threadIdx.x, lane = tid & 31, wid = tid >> 5;
    const int wm0 = (wid & 3) * 32;      // 4 warps along M
    const int wn0 = (wid >> 2) * 32;     // 2 warps along N
    const int m0 = blockIdx.y * 128, n0 = blockIdx.x * 64, z = blockIdx.z;

    const int n1 = K / 128;              // physical 128B chunks
    const int rowlen = 2 * K;

    A += (size_t)z * sA + (size_t)m0 * rowlen;
    B += (size_t)z * sB + (size_t)n0 * rowlen;

    auto load_stage = [&](int st, int c) {
        const uint32_t base = sb + st * STG;
        #pragma unroll
        for (int i = 0; i < 12; i++) {
            const int idx = tid + i * 256;      // 384 rows x 8 chunks of 16B
            const int row = idx >> 3, ch = idx & 7;
            const uint32_t dst = base + row * ROWB + ch * 16;
            const int8_t* src;
            if (row < 128)       src = A + (size_t)row * rowlen + c * 128 + ch * 16;
            else if (row < 256)  src = A + (size_t)(row - 128) * rowlen + K + c * 128 + ch * 16;
            else if (row < 320)  src = B + (size_t)(row - 256) * rowlen + c * 128 + ch * 16;
            else                 src = B + (size_t)(row - 320) * rowlen + K + c * 128 + ch * 16;
            cp16(dst, src);
        }
    };

    int acc0[2][4][4], acc1[2][4][4];
    #pragma unroll
    for (int i = 0; i < 2; i++)
        #pragma unroll
        for (int j = 0; j < 4; j++)
            #pragma unroll
            for (int q = 0; q < 4; q++) { acc0[i][j][q] = 0; acc1[i][j][q] = 0; }

    load_stage(0, 0); CP_COMMIT();

    const int arow = wm0 + (lane & 15);
    const int acsel = (lane >> 4);
    const int brow = wn0 + (lane & 7) + ((lane >> 4) & 1) * 8;
    const int bcsel = (lane >> 3) & 1;

    for (int c = 0; c < n1; c++) {
        __syncthreads();                 // readers of slot (c+1)&1 (iter c-1) done
        if (c + 1 < n1) load_stage((c + 1) & 1, c + 1);
        CP_COMMIT();
        asm volatile("cp.async.wait_group 1;" ::: "memory");   // chunk c resident
        __syncthreads();                 // chunk c visible to all warps

        const uint32_t sa = sb + (c & 1) * STG;

        #pragma unroll
        for (int ks = 0; ks < 4; ks++) {
            uint32_t aq1[2][4], aq2[2][4], bq1[2][4], bq2[2][4];
            const uint32_t ac = (ks * 2 + acsel) * 16;
            const uint32_t bc = (ks * 2 + bcsel) * 16;
            #pragma unroll
            for (int i = 0; i < 2; i++) {
                ldm4(aq1[i], sa + (arow + i * 16) * ROWB + ac);
                ldm4(aq2[i], sa + (128 + arow + i * 16) * ROWB + ac);
            }
            #pragma unroll
            for (int j = 0; j < 2; j++) {
                ldm4(bq1[j], sa + (256 + brow + j * 16) * ROWB + bc);
                ldm4(bq2[j], sa + (320 + brow + j * 16) * ROWB + bc);
            }
            #pragma unroll
            for (int i = 0; i < 2; i++)
                #pragma unroll
                for (int jn = 0; jn < 4; jn++) {
                    const uint32_t b1lo = bq1[jn >> 1][(jn & 1) * 2];
                    const uint32_t b1hi = bq1[jn >> 1][(jn & 1) * 2 + 1];
                    const uint32_t b2lo = bq2[jn >> 1][(jn & 1) * 2];
                    const uint32_t b2hi = bq2[jn >> 1][(jn & 1) * 2 + 1];
                    mma16832(acc0[i][jn], aq1[i], b1lo, b1hi);   // q1*q1
                    mma16832(acc1[i][jn], aq1[i], b2lo, b2hi);   // q1*q2
                    mma16832(acc1[i][jn], aq2[i], b1lo, b1hi);   // q2*q1
                }
        }
    }

    // -------- epilogue --------
    const int mb = m0 + wm0 + (lane >> 2);
    const int nb = n0 + wn0 + (lane & 3) * 2;
    #pragma unroll
    for (int i = 0; i < 2; i++) {
        #pragma unroll
        for (int half = 0; half < 2; half++) {
            const int m = mb + i * 16 + half * 8;
            const float sAm = sAarr[z * sAstr + m] * scale;
            const float br = bias_row ? bias_row[m] : 0.f;
            #pragma unroll
            for (int jn = 0; jn < 4; jn++) {
                const int n = nb + jn * 8;
                float f0 = (float)acc0[i][jn][half * 2 + 0]
                         + (float)acc1[i][jn][half * 2 + 0] * INV252;
                float f1 = (float)acc0[i][jn][half * 2 + 1]
                         + (float)acc1[i][jn][half * 2 + 1] * INV252;
                float v0 = f0 * sAm * sBarr[z * sBstr + n] + br;
                float v1 = f1 * sAm * sBarr[z * sBstr + n + 1] + br;
                if (bias_col) { v0 += bias_col[n]; v1 += bias_col[n + 1]; }
                if (EPI == 0) {
                    *(float2*)&Cf[(size_t)z * sC + (size_t)m * ldc + n] = make_float2(v0, v1);
                } else {
                    float q0 = fminf(fmaxf(v0 * SSCALE, -32000.f), 32000.f);
                    float q1 = fminf(fmaxf(v1 * SSCALE, -32000.f), 32000.f);
                    short2 o;
                    o.x = (short)(int)rintf(q0);
                    o.y = (short)(int)rintf(q1);
                    *(short2*)&Cs[(size_t)z * sC + (size_t)m * ldc + n] = o;
                }
            }
        }
    }
}

// -------------------- quantization helpers --------------------------------
__device__ __forceinline__ float clamp127(float q) {
    return fminf(127.f, fmaxf(-127.f, q));
}

__device__ __forceinline__ void rowquant_body(const float* __restrict__ src, int len,
                                              int8_t* __restrict__ dst,
                                              float* __restrict__ sOut)
{
    const int t = threadIdx.x;
    float m = 0.f;
    for (int i = t; i < len; i += 256) m = fmaxf(m, fabsf(src[i]));
    #pragma unroll
    for (int o = 16; o > 0; o >>= 1) m = fmaxf(m, __shfl_xor_sync(~0u, m, o));
    __shared__ float sm[8];
    if ((t & 31) == 0) sm[t >> 5] = m;
    __syncthreads();
    float mm = sm[0];
    #pragma unroll
    for (int i = 1; i < 8; i++) mm = fmaxf(mm, sm[i]);

    const float s1 = mm * (1.f / 127.f);
    const float i1 = (mm > 0.f) ? (127.f / mm) : 0.f;
    const float i2 = i1 * 252.f;

    for (int i = t; i < len; i += 256) {
        float x = src[i];
        float q1 = clamp127(rintf(x * i1));
        float r = x - q1 * s1;
        float q2 = clamp127(rintf(r * i2));
        dst[i] = (int8_t)(int)q1;
        dst[len + i] = (int8_t)(int)q2;
    }
    if (t == 0) *sOut = s1;
}

__global__ void __launch_bounds__(256)
rowquantW(const float* __restrict__ Wq, const float* __restrict__ Wk,
          const float* __restrict__ Wv,
          int8_t* __restrict__ Wq2, int8_t* __restrict__ Wk2, int8_t* __restrict__ Wv2,
          float* __restrict__ sWq, float* __restrict__ sWk, float* __restrict__ sWv)
{
    const int r = blockIdx.x;
    const float* src; int8_t* dst; float* sOut;
    if (r < CQK)            { src = Wq + (size_t)r * CIN;          dst = Wq2 + (size_t)r * 2 * CIN;          sOut = sWq + r; }
    else if (r < 2 * CQK)   { int rr = r - CQK;   src = Wk + (size_t)rr * CIN; dst = Wk2 + (size_t)rr * 2 * CIN; sOut = sWk + rr; }
    else                    { int rr = r - 2*CQK; src = Wv + (size_t)rr * CIN; dst = Wv2 + (size_t)rr * 2 * CIN; sOut = sWv + rr; }
    rowquant_body(src, CIN, dst, sOut);
}

__global__ void __launch_bounds__(256)
rowquantQK(const float* __restrict__ Qf, const float* __restrict__ Kf,
           int8_t* __restrict__ Q2, int8_t* __restrict__ K2,
           float* __restrict__ sQ, float* __restrict__ sK)
{
    const size_t r = blockIdx.x;
    const size_t nrows = (size_t)NB * NPIX;
    if (r < nrows)
        rowquant_body(Qf + r * CQK, CQK, Q2 + r * 2 * CQK, sQ + r);
    else {
        const size_t rr = r - nrows;
        rowquant_body(Kf + rr * CQK, CQK, K2 + rr * 2 * CQK, sK + rr);
    }
}

__global__ void __launch_bounds__(256)
rowquantV(const float* __restrict__ Vf, int8_t* __restrict__ V2, float* __restrict__ sV)
{
    const size_t r = blockIdx.x;
    rowquant_body(Vf + r * NPIX, NPIX, V2 + r * 2 * NPIX, sV + r);
}

// Chunked column-max with atomicMax (non-negative floats as ints: monotone;
// deterministic across graph replays). grid (NPIX/256, NB, 8).
__global__ void __launch_bounds__(256)
colmax8(const float* __restrict__ Xq, const float* __restrict__ Xk,
        float* __restrict__ sXq, float* __restrict__ sXk)
{
    const int n = blockIdx.x * 256 + threadIdx.x;
    const int b = blockIdx.y;
    const int zz = blockIdx.z;
    const float* X = (zz & 1) ? Xk : Xq;
    float* sX = (zz & 1) ? sXk : sXq;
    const int c0 = (zz >> 1) * (CIN / 4);
    const float* p = X + (size_t)b * CIN * NPIX + (size_t)c0 * NPIX + n;
    float m = 0.f;
    for (int ci = 0; ci < CIN / 4; ci++) m = fmaxf(m, fabsf(p[(size_t)ci * NPIX]));
    atomicMax((int*)&sX[b * NPIX + n], __float_as_int(m * (1.f / 127.f)));
}

// Merged transpose + quantize for both inputs: grid (NPIX/32, CIN/32, 2*NB)
__global__ void __launch_bounds__(256)
transpose_quant2(const float* __restrict__ Xq, const float* __restrict__ Xk,
                 const float* __restrict__ sXq, const float* __restrict__ sXk,
                 int8_t* __restrict__ Xq2, int8_t* __restrict__ Xk2)
{
    __shared__ float t[32][33];
    const int zz = blockIdx.z;
    const int b = zz & (NB - 1);
    const int which = zz >> 2;
    const float* X = which ? Xk : Xq;
    const float* sX = which ? sXk : sXq;
    int8_t* X2 = which ? Xk2 : Xq2;

    const int n0 = blockIdx.x * 32, c0 = blockIdx.y * 32;
    const int tx = threadIdx.x & 31, ty = threadIdx.x >> 5;
    const float* Xb = X + (size_t)b * CIN * NPIX;
    #pragma unroll
    for (int r = 0; r < 4; r++)
        t[ty + r * 8][tx] = Xb[(size_t)(c0 + ty + r * 8) * NPIX + n0 + tx];
    __syncthreads();
    const size_t ob = (size_t)b * NPIX * 2 * CIN;
    #pragma unroll
    for (int r = 0; r < 4; r++) {
        const int n = n0 + ty + r * 8;
        const int c = c0 + tx;
        const float v = t[tx][ty + r * 8];
        const float s1 = sX[b * NPIX + n];
        const float i1 = (s1 > 0.f) ? (1.f / s1) : 0.f;
        float q1 = clamp127(rintf(v * i1));
        float rr = v - q1 * s1;
        float q2 = clamp127(rintf(rr * i1 * 252.f));
        const size_t row = ob + (size_t)n * (2 * CIN);
        X2[row + c] = (int8_t)(int)q1;
        X2[row + CIN + c] = (int8_t)(int)q2;
    }
}

// -------- softmax: int16 S rows -> int8 attn [q1|q2] + scale ---------------
__global__ void __launch_bounds__(256)
softmax2_q(const int16_t* __restrict__ S, int8_t* __restrict__ A2,
           float* __restrict__ sAt)
{
    const size_t rb = (size_t)blockIdx.x * NPIX;
    const int16_t* row = S + rb;
    int8_t* orow = A2 + (size_t)blockIdx.x * (2 * NPIX);
    const int t = threadIdx.x;
    float v[16];
    float m = -1e30f;
    #pragma unroll
    for (int i = 0; i < 16; i++) {
        v[i] = (float)row[t + i * 256] * INVSSCALE;
        m = fmaxf(m, v[i]);
    }
    #pragma unroll
    for (int o = 16; o > 0; o >>= 1) m = fmaxf(m, __shfl_xor_sync(~0u, m, o));
    __shared__ float smax[8], ssum[8];
    if ((t & 31) == 0) smax[t >> 5] = m;
    __syncthreads();
    float mm = smax[0];
    #pragma unroll
    for (int i = 1; i < 8; i++) mm = fmaxf(mm, smax[i]);
    float s = 0.f;
    #pragma unroll
    for (int i = 0; i < 16; i++) { v[i] = __expf(v[i] - mm); s += v[i]; }
    #pragma unroll
    for (int o = 16; o > 0; o >>= 1) s += __shfl_xor_sync(~0u, s, o);
    if ((t & 31) == 0) ssum[t >> 5] = s;
    __syncthreads();
    float tot = 0.f;
    #pragma unroll
    for (int i = 0; i < 8; i++) tot += ssum[i];
    const float inv = 1.0f / tot;

    #pragma unroll
    for (int i = 0; i < 16; i++) {
        const int k = t + i * 256;
        float f = v[i] * 127.f;
        float q1 = clamp127(rintf(f));
        float q2 = clamp127(rintf((f - q1) * 252.f));
        orow[k] = (int8_t)(int)q1;
        orow[NPIX + k] = (int8_t)(int)q2;
    }
    if (t == 0) sAt[blockIdx.x] = inv * (1.f / 127.f);
}

// ------------------------------- host -------------------------------------
extern "C" void kernel_launch(void* const* d_in, const int* in_sizes, int n_in,
                              void* d_out, int out_size)
{
    const float* qfeat = (const float*)d_in[0];
    const float* kfeat = (const float*)d_in[1];
    const float* Wq = (const float*)d_in[2];
    const float* bq = (const float*)d_in[3];
    const float* Wk = (const float*)d_in[4];
    const float* bk = (const float*)d_in[5];
    const float* Wv = (const float*)d_in[6];
    const float* bv = (const float*)d_in[7];
    float* out = (float*)d_out;

    void *Xq2, *Xk2, *Wq2, *Wk2, *Wv2, *Qf, *Kf, *Vf, *Q2, *K2, *V2, *Sd, *A2;
    void *sXq, *sXk, *sWq, *sWk, *sWv, *sQ, *sK, *sV, *sAt;
    cudaGetSymbolAddress(&Xq2, g_Xq2);
    cudaGetSymbolAddress(&Xk2, g_Xk2);
    cudaGetSymbolAddress(&Wq2, g_Wq2);
    cudaGetSymbolAddress(&Wk2, g_Wk2);
    cudaGetSymbolAddress(&Wv2, g_Wv2);
    cudaGetSymbolAddress(&Qf, g_Qf);
    cudaGetSymbolAddress(&Kf, g_Kf);
    cudaGetSymbolAddress(&Vf, g_Vf);
    cudaGetSymbolAddress(&Q2, g_Q2);
    cudaGetSymbolAddress(&K2, g_K2);
    cudaGetSymbolAddress(&V2, g_V2);
    cudaGetSymbolAddress(&Sd, g_S);
    cudaGetSymbolAddress(&A2, g_A2);
    cudaGetSymbolAddress(&sXq, g_sXq);
    cudaGetSymbolAddress(&sXk, g_sXk);
    cudaGetSymbolAddress(&sWq, g_sWq);
    cudaGetSymbolAddress(&sWk, g_sWk);
    cudaGetSymbolAddress(&sWv, g_sWv);
    cudaGetSymbolAddress(&sQ, g_sQ);
    cudaGetSymbolAddress(&sK, g_sK);
    cudaGetSymbolAddress(&sV, g_sV);
    cudaGetSymbolAddress(&sAt, g_sAt);

    cudaFuncSetAttribute((const void*)gemm_s8<0>, cudaFuncAttributeMaxDynamicSharedMemorySize, GSMEM);
    cudaFuncSetAttribute((const void*)gemm_s8<1>, cudaFuncAttributeMaxDynamicSharedMemorySize, GSMEM);

    // 1) weights quantization (merged)
    rowquantW<<<2 * CQK + COUT, 256>>>(Wq, Wk, Wv,
        (int8_t*)Wq2, (int8_t*)Wk2, (int8_t*)Wv2,
        (float*)sWq, (float*)sWk, (float*)sWv);

    // 2) column maxima (chunked + atomicMax)
    colmax8<<<dim3(NPIX / 256, NB, 8), 256>>>(qfeat, kfeat, (float*)sXq, (float*)sXk);

    // 3) transpose + quantize both inputs (merged)
    transpose_quant2<<<dim3(NPIX / 32, CIN / 32, 2 * NB), 256>>>(
        qfeat, kfeat, (const float*)sXq, (const float*)sXk,
        (int8_t*)Xq2, (int8_t*)Xk2);

    // 4) Q proj: M=4096, N=256, K=512
    gemm_s8<0><<<dim3(CQK / 64, NPIX / 128, NB), 256, GSMEM>>>(
        (const int8_t*)Xq2, (size_t)NPIX * 2 * CIN,
        (const int8_t*)Wq2, 0, CIN,
        (float*)Qf, nullptr, (size_t)CQK, (size_t)NPIX * CQK,
        (const float*)sXq, (size_t)NPIX, (const float*)sWq, 0,
        nullptr, bq, 1.0f);

    // 5) K proj  <- profiled launch slot
    gemm_s8<0><<<dim3(CQK / 64, NPIX / 128, NB), 256, GSMEM>>>(
        (const int8_t*)Xk2, (size_t)NPIX * 2 * CIN,
        (const int8_t*)Wk2, 0, CIN,
        (float*)Kf, nullptr, (size_t)CQK, (size_t)NPIX * CQK,
        (const float*)sXk, (size_t)NPIX, (const float*)sWk, 0,
        nullptr, bk, 1.0f);

    // 6) V proj: M=512, N=4096, K=512
    gemm_s8<0><<<dim3(NPIX / 64, COUT / 128, NB), 256, GSMEM>>>(
        (const int8_t*)Wv2, 0,
        (const int8_t*)Xk2, (size_t)NPIX * 2 * CIN, CIN,
        (float*)Vf, nullptr, (size_t)NPIX, (size_t)COUT * NPIX,
        (const float*)sWv, 0, (const float*)sXk, (size_t)NPIX,
        bv, nullptr, 1.0f);

    // 7) quantize Q+K (merged) and V
    rowquantQK<<<2 * NB * NPIX, 256>>>((const float*)Qf, (const float*)Kf,
        (int8_t*)Q2, (int8_t*)K2, (float*)sQ, (float*)sK);
    rowquantV<<<NB * COUT, 256>>>((const float*)Vf, (int8_t*)V2, (float*)sV);

    // 8) sim: S = int16( (1/16) Q2 . K2^T * SSCALE ), M=N=4096, K=256
    gemm_s8<1><<<dim3(NPIX / 64, NPIX / 128, NB), 256, GSMEM>>>(
        (const int8_t*)Q2, (size_t)NPIX * 2 * CQK,
        (const int8_t*)K2, (size_t)NPIX * 2 * CQK, CQK,
        nullptr, (int16_t*)Sd, (size_t)NPIX, (size_t)NPIX * NPIX,
        (const float*)sQ, (size_t)NPIX, (const float*)sK, (size_t)NPIX,
        nullptr, nullptr, 0.0625f);

    // 9) softmax -> int8 attn [q1|q2] + scales
    softmax2_q<<<NB * NPIX, 256>>>((const int16_t*)Sd, (int8_t*)A2, (float*)sAt);

    // 10) ctx: out = V2 . A2^T, M=512, N=4096, K=4096
    gemm_s8<0><<<dim3(NPIX / 64, COUT / 128, NB), 256, GSMEM>>>(
        (const int8_t*)V2, (size_t)COUT * 2 * NPIX,
        (const int8_t*)A2, (size_t)NPIX * 2 * NPIX, NPIX,
        out, nullptr, (size_t)NPIX, (size_t)COUT * NPIX,
        (const float*)sV, (size_t)COUT, (const float*)sAt, (size_t)NPIX,
        nullptr, nullptr, 1.0f);
}